// round 2
// baseline (speedup 1.0000x reference)
#include <cuda_runtime.h>

typedef unsigned long long ull;

#define NB 8
#define NN 170
#define NT 336
#define TH 168          // folded length
#define GRID_BN (NB*NN) // 1360
#define SP 68           // padded row stride (floats) for 64-wide matrices
#define SLOT 4368       // 64*68 + 16 pad (floats)

// smem layout (floats):
//  [0]      XR   (64 x SP)
//  [1*SLOT] XI
//  [2*SLOT] QR      (aliased by xs fold buffer in phase 0/1)
//  [3*SLOT] QI
//  [4*SLOT] KTR  [e][m]  (later reused as attention-output OUTR [l][e])
//  [5*SLOT] KTI  (later OUTI)
//  [6*SLOT] VTR  [e][m]
//  [7*SLOT] VTI
//  then WRs(4096) pad WIs(4096) pad, then Pbuf(8 warps * 128)
#define W_OFF   (8*SLOT)
#define PB_OFF  (W_OFF + 2*4112)
#define SMEM_FLOATS (PB_OFF + 1024)
#define SMEM_BYTES  (SMEM_FLOATS*4)

// ------------------------------------------------------------------
// twiddle tables (built by init kernel each launch; deterministic)
// ------------------------------------------------------------------
__device__ float g_FC[TH*64];   // cos(2*pi*j*t/168)
__device__ float g_FS[TH*64];   // -sin(...)
__device__ float g_GC[TH*64];   // w_j * cos(...)
__device__ float g_GS[TH*64];   // -w_j * sin(...)   (j=0 -> 0: irfft drops Im(X0))

__global__ void twiddle_init_kernel() {
    int idx = blockIdx.x * blockDim.x + threadIdx.x;
    if (idx >= TH*64) return;
    int t = idx >> 6;
    int j = idx & 63;
    int r = (t * j) % TH;                       // exact periodic reduction
    float s, c;
    sincospif((float)r * (1.0f/84.0f), &s, &c); // angle = 2*pi*r/168
    g_FC[idx] = c;
    g_FS[idx] = -s;
    float wj = (j == 0) ? (1.0f/336.0f) : (2.0f/336.0f);
    g_GC[idx] = wj * c;
    g_GS[idx] = -wj * s;
}

// ------------------------------------------------------------------
// packed f32x2 helpers
// ------------------------------------------------------------------
__device__ __forceinline__ ull pk2(float lo, float hi) {
    ull r;
    asm("mov.b64 %0, {%1, %2};" : "=l"(r) : "f"(lo), "f"(hi));
    return r;
}
__device__ __forceinline__ ull pkdup(float v) { return pk2(v, v); }
__device__ __forceinline__ ull fma2(ull a, ull b, ull c) {
    ull d;
    asm("fma.rn.f32x2 %0, %1, %2, %3;" : "=l"(d) : "l"(a), "l"(b), "l"(c));
    return d;
}
__device__ __forceinline__ float2 up2(ull v) {
    float2 f;
    asm("mov.b64 {%0, %1}, %2;" : "=f"(f.x), "=f"(f.y) : "l"(v));
    return f;
}
#define SGN2 0x8000000080000000ULL

// stage one 64x64 complex weight into smem
__device__ __forceinline__ void stage_w(float* WRs, float* WIs,
                                        const float* wr, const float* wi, int tid) {
    #pragma unroll
    for (int k = 0; k < 4; k++) {
        int i = tid + k * 256;
        ((float4*)WRs)[i] = __ldg((const float4*)wr + i);
        ((float4*)WIs)[i] = __ldg((const float4*)wi + i);
    }
}

// ------------------------------------------------------------------
// complex 64x64x64 GEMM: C = A * W   (A stride SP, W stride 64)
// TRANS=1: store C transposed [e][m] with stride SP
// 256 threads: thread -> 4 m x 4 e outputs. All f32x2.
// ------------------------------------------------------------------
template<int TRANS>
__device__ __forceinline__ void cgemm64(
    const float* __restrict__ AR, const float* __restrict__ AI,
    const float* __restrict__ WR, const float* __restrict__ WI,
    float* __restrict__ CR, float* __restrict__ CI, int tid)
{
    const int m0 = (tid >> 4) * 4;
    const int e0 = (tid & 15) * 4;
    ull accR[4][2], accI[4][2];
    #pragma unroll
    for (int mm = 0; mm < 4; mm++) {
        accR[mm][0] = 0; accR[mm][1] = 0;
        accI[mm][0] = 0; accI[mm][1] = 0;
    }
    #pragma unroll 2
    for (int d4 = 0; d4 < 64; d4 += 4) {
        float4 ar[4], ai[4];
        #pragma unroll
        for (int mm = 0; mm < 4; mm++) {
            ar[mm] = *(const float4*)&AR[(m0+mm)*SP + d4];
            ai[mm] = *(const float4*)&AI[(m0+mm)*SP + d4];
        }
        #pragma unroll
        for (int dd = 0; dd < 4; dd++) {
            float4 wr4 = *(const float4*)&WR[(d4+dd)*64 + e0];
            float4 wi4 = *(const float4*)&WI[(d4+dd)*64 + e0];
            ull wr0 = pk2(wr4.x, wr4.y), wr1 = pk2(wr4.z, wr4.w);
            ull wi0 = pk2(wi4.x, wi4.y), wi1 = pk2(wi4.z, wi4.w);
            ull nwi0 = wi0 ^ SGN2, nwi1 = wi1 ^ SGN2;
            #pragma unroll
            for (int mm = 0; mm < 4; mm++) {
                float a = ((const float*)&ar[mm])[dd];
                float b = ((const float*)&ai[mm])[dd];
                ull ad = pkdup(a), bd = pkdup(b);
                accR[mm][0] = fma2(ad, wr0,  accR[mm][0]);
                accR[mm][1] = fma2(ad, wr1,  accR[mm][1]);
                accI[mm][0] = fma2(ad, wi0,  accI[mm][0]);
                accI[mm][1] = fma2(ad, wi1,  accI[mm][1]);
                accR[mm][0] = fma2(bd, nwi0, accR[mm][0]);
                accR[mm][1] = fma2(bd, nwi1, accR[mm][1]);
                accI[mm][0] = fma2(bd, wr0,  accI[mm][0]);
                accI[mm][1] = fma2(bd, wr1,  accI[mm][1]);
            }
        }
    }
    #pragma unroll
    for (int mm = 0; mm < 4; mm++) {
        float2 r0 = up2(accR[mm][0]), r1 = up2(accR[mm][1]);
        float2 i0 = up2(accI[mm][0]), i1 = up2(accI[mm][1]);
        if (!TRANS) {
            *(float4*)&CR[(m0+mm)*SP + e0] = make_float4(r0.x, r0.y, r1.x, r1.y);
            *(float4*)&CI[(m0+mm)*SP + e0] = make_float4(i0.x, i0.y, i1.x, i1.y);
        } else {
            int m = m0 + mm;
            CR[(e0+0)*SP + m] = r0.x; CR[(e0+1)*SP + m] = r0.y;
            CR[(e0+2)*SP + m] = r1.x; CR[(e0+3)*SP + m] = r1.y;
            CI[(e0+0)*SP + m] = i0.x; CI[(e0+1)*SP + m] = i0.y;
            CI[(e0+2)*SP + m] = i1.x; CI[(e0+3)*SP + m] = i1.y;
        }
    }
}

// ------------------------------------------------------------------
// main kernel: one CTA per (b, n)
// ------------------------------------------------------------------
__global__ void __launch_bounds__(256, 1) spectral_attn_kernel(
    const float* __restrict__ x,
    const float* __restrict__ Wq_r, const float* __restrict__ Wq_i,
    const float* __restrict__ Wk_r, const float* __restrict__ Wk_i,
    const float* __restrict__ Wv_r, const float* __restrict__ Wv_i,
    const float* __restrict__ Wo_r, const float* __restrict__ Wo_i,
    float* __restrict__ y)
{
    extern __shared__ float sm[];
    float* XR   = sm;
    float* XI   = sm + 1*SLOT;
    float* QRb  = sm + 2*SLOT;
    float* QIb  = sm + 3*SLOT;
    float* KTRb = sm + 4*SLOT;   // K^T [e][m]; reused as OUTR [l][e]
    float* KTIb = sm + 5*SLOT;   // reused as OUTI
    float* VTRb = sm + 6*SLOT;   // V^T [e][m]
    float* VTIb = sm + 7*SLOT;
    float* WRs  = sm + W_OFF;
    float* WIs  = sm + W_OFF + 4112;
    float* PB   = sm + PB_OFF;
    float* xs   = QRb;           // 168x64 fold buffer (alias, dead before Q GEMM)

    const int tid = threadIdx.x;
    const int bn  = blockIdx.x;
    const float* xg = x + (size_t)bn * (NT*64);
    float*       yg = y + (size_t)bn * (NT*64);

    // ---- Phase 0: fold x[t] + x[t+168] ----
    for (int i = tid; i < TH*16; i += 256) {
        int t = i >> 4, c = i & 15;
        float4 a = __ldg((const float4*)(xg + t*64) + c);
        float4 b = __ldg((const float4*)(xg + (t+TH)*64) + c);
        *(float4*)&xs[t*64 + c*4] = make_float4(a.x+b.x, a.y+b.y, a.z+b.z, a.w+b.w);
    }
    __syncthreads();

    // ---- Phase 1: forward DFT  X[j,d] = sum_t xs[t,d] * (FC + i FS) ----
    {
        const int j0 = (tid >> 4) * 4;
        const int d0 = (tid & 15) * 4;
        ull aR[4][2], aI[4][2];
        #pragma unroll
        for (int jj = 0; jj < 4; jj++) { aR[jj][0]=0; aR[jj][1]=0; aI[jj][0]=0; aI[jj][1]=0; }
        #pragma unroll 2
        for (int t = 0; t < TH; t++) {
            float4 c4 = __ldg((const float4*)&g_FC[t*64 + j0]);
            float4 s4 = __ldg((const float4*)&g_FS[t*64 + j0]);
            float4 xv = *(const float4*)&xs[t*64 + d0];
            ull x01 = pk2(xv.x, xv.y), x23 = pk2(xv.z, xv.w);
            #pragma unroll
            for (int jj = 0; jj < 4; jj++) {
                ull cd = pkdup(((const float*)&c4)[jj]);
                ull sd = pkdup(((const float*)&s4)[jj]);
                aR[jj][0] = fma2(cd, x01, aR[jj][0]);
                aR[jj][1] = fma2(cd, x23, aR[jj][1]);
                aI[jj][0] = fma2(sd, x01, aI[jj][0]);
                aI[jj][1] = fma2(sd, x23, aI[jj][1]);
            }
        }
        #pragma unroll
        for (int jj = 0; jj < 4; jj++) {
            float2 r0 = up2(aR[jj][0]), r1 = up2(aR[jj][1]);
            float2 i0 = up2(aI[jj][0]), i1 = up2(aI[jj][1]);
            *(float4*)&XR[(j0+jj)*SP + d0] = make_float4(r0.x, r0.y, r1.x, r1.y);
            *(float4*)&XI[(j0+jj)*SP + d0] = make_float4(i0.x, i0.y, i1.x, i1.y);
        }
    }
    // NOTE: no sync needed here; the stage_w/sync below orders xs-reads vs QR-writes.

    // ---- Phase 2: two attention layers ----
    const int wid = tid >> 5, ln = tid & 31;
    #pragma unroll 1
    for (int layer = 0; layer < 2; layer++) {
        const float* wq_r = Wq_r + layer*4096; const float* wq_i = Wq_i + layer*4096;
        const float* wk_r = Wk_r + layer*4096; const float* wk_i = Wk_i + layer*4096;
        const float* wv_r = Wv_r + layer*4096; const float* wv_i = Wv_i + layer*4096;
        const float* wo_r = Wo_r + layer*4096; const float* wo_i = Wo_i + layer*4096;

        stage_w(WRs, WIs, wq_r, wq_i, tid); __syncthreads();
        cgemm64<0>(XR, XI, WRs, WIs, QRb, QIb, tid); __syncthreads();

        stage_w(WRs, WIs, wk_r, wk_i, tid); __syncthreads();
        cgemm64<1>(XR, XI, WRs, WIs, KTRb, KTIb, tid); __syncthreads();

        stage_w(WRs, WIs, wv_r, wv_i, tid); __syncthreads();
        cgemm64<1>(XR, XI, WRs, WIs, VTRb, VTIb, tid); __syncthreads();

        // ---- fused scores -> softmax -> AV, one warp per head ----
        {
            const int h = wid;
            // preload this head's K into registers, packed over (m=ln, m=ln+32)
            ull kpr[8], kpi[8];
            #pragma unroll
            for (int d = 0; d < 8; d++) {
                const float* pr = KTRb + (h*8+d)*SP;
                const float* pi = KTIb + (h*8+d)*SP;
                kpr[d] = pk2(pr[ln], pr[ln+32]);
                kpi[d] = pk2(pi[ln], pi[ln+32]);
            }
            __syncthreads();   // all K reads done before OUT overwrites KT space
            float* OUTR = KTRb;
            float* OUTI = KTIb;
            float* Pw = PB + wid*128;

            // AV lane roles: lanes 0-15 -> row l, lanes 16-31 -> row l+1
            const int rhalf = ln >> 4;
            const int qq = ln & 15;
            const int dAV = qq & 7;
            const bool isI = (qq & 8) != 0;
            const float* vrow = (isI ? VTIb : VTRb) + (h*8 + dAV)*SP;
            float* orow = isI ? OUTI : OUTR;

            const float SCALE = 0.3535533905932738f; // 1/sqrt(8)
            for (int l = 0; l < 64; l += 2) {
                float sA[2], sB[2];
                #pragma unroll
                for (int r = 0; r < 2; r++) {
                    int row = l + r;
                    float4 qr0 = *(const float4*)&QRb[row*SP + h*8];
                    float4 qr1 = *(const float4*)&QRb[row*SP + h*8 + 4];
                    float4 qi0 = *(const float4*)&QIb[row*SP + h*8];
                    float4 qi1 = *(const float4*)&QIb[row*SP + h*8 + 4];
                    ull a0 = 0, a1 = 0, a2 = 0, a3 = 0;
                    a0 = fma2(pkdup(qr0.x), kpr[0], a0);
                    a1 = fma2(pkdup(qr0.y), kpr[1], a1);
                    a2 = fma2(pkdup(qr0.z), kpr[2], a2);
                    a3 = fma2(pkdup(qr0.w), kpr[3], a3);
                    a0 = fma2(pkdup(qr1.x), kpr[4], a0);
                    a1 = fma2(pkdup(qr1.y), kpr[5], a1);
                    a2 = fma2(pkdup(qr1.z), kpr[6], a2);
                    a3 = fma2(pkdup(qr1.w), kpr[7], a3);
                    a0 = fma2(pkdup(qi0.x), kpi[0], a0);
                    a1 = fma2(pkdup(qi0.y), kpi[1], a1);
                    a2 = fma2(pkdup(qi0.z), kpi[2], a2);
                    a3 = fma2(pkdup(qi0.w), kpi[3], a3);
                    a0 = fma2(pkdup(qi1.x), kpi[4], a0);
                    a1 = fma2(pkdup(qi1.y), kpi[5], a1);
                    a2 = fma2(pkdup(qi1.z), kpi[6], a2);
                    a3 = fma2(pkdup(qi1.w), kpi[7], a3);
                    float2 f0 = up2(a0), f1 = up2(a1), f2 = up2(a2), f3 = up2(a3);
                    sA[r] = ((f0.x+f1.x)+(f2.x+f3.x)) * SCALE;  // score[m=ln]
                    sB[r] = ((f0.y+f1.y)+(f2.y+f3.y)) * SCALE;  // score[m=ln+32]
                }
                float mx0 = fmaxf(sA[0], sB[0]);
                float mx1 = fmaxf(sA[1], sB[1]);
                #pragma unroll
                for (int o = 16; o; o >>= 1) {
                    mx0 = fmaxf(mx0, __shfl_xor_sync(0xffffffffu, mx0, o));
                    mx1 = fmaxf(mx1, __shfl_xor_sync(0xffffffffu, mx1, o));
                }
                float e00 = __expf(sA[0]-mx0), e01 = __expf(sB[0]-mx0);
                float e10 = __expf(sA[1]-mx1), e11 = __expf(sB[1]-mx1);
                float su0 = e00 + e01, su1 = e10 + e11;
                #pragma unroll
                for (int o = 16; o; o >>= 1) {
                    su0 += __shfl_xor_sync(0xffffffffu, su0, o);
                    su1 += __shfl_xor_sync(0xffffffffu, su1, o);
                }
                float inv0 = 1.0f / su0, inv1 = 1.0f / su1;
                Pw[ln]       = e00 * inv0;  Pw[ln+32]    = e01 * inv0;
                Pw[64+ln]    = e10 * inv1;  Pw[64+ln+32] = e11 * inv1;
                __syncwarp();
                // AV: out[row, h*8+dAV] = sum_m p[m] * v[m]
                const float* pr = Pw + rhalf*64;
                float ac0 = 0.0f, ac1 = 0.0f;
                #pragma unroll
                for (int m4 = 0; m4 < 64; m4 += 8) {
                    float4 p4 = *(const float4*)&pr[m4];
                    float4 v4 = *(const float4*)&vrow[m4];
                    ac0 = fmaf(p4.x, v4.x, ac0); ac0 = fmaf(p4.y, v4.y, ac0);
                    ac0 = fmaf(p4.z, v4.z, ac0); ac0 = fmaf(p4.w, v4.w, ac0);
                    float4 p5 = *(const float4*)&pr[m4+4];
                    float4 v5 = *(const float4*)&vrow[m4+4];
                    ac1 = fmaf(p5.x, v5.x, ac1); ac1 = fmaf(p5.y, v5.y, ac1);
                    ac1 = fmaf(p5.z, v5.z, ac1); ac1 = fmaf(p5.w, v5.w, ac1);
                }
                orow[(l+rhalf)*SP + h*8 + dAV] = ac0 + ac1;
                __syncwarp();
            }
        }
        // ---- Wo GEMM: X = OUT * Wo ----
        stage_w(WRs, WIs, wo_r, wo_i, tid); __syncthreads();
        cgemm64<0>(KTRb, KTIb, WRs, WIs, XR, XI, tid); __syncthreads();
    }

    // ---- Phase 3: inverse DFT, period-168 output stored twice ----
    {
        const int tg = tid >> 3;
        const int d0 = (tid & 7) * 8;
        for (int t = tg; t < TH; t += 32) {
            ull a0 = 0, a1 = 0, a2 = 0, a3 = 0;
            #pragma unroll 2
            for (int j4 = 0; j4 < 64; j4 += 4) {
                float4 gc4 = __ldg((const float4*)&g_GC[t*64 + j4]);
                float4 gs4 = __ldg((const float4*)&g_GS[t*64 + j4]);
                #pragma unroll
                for (int jj = 0; jj < 4; jj++) {
                    int j = j4 + jj;
                    float4 xr0 = *(const float4*)&XR[j*SP + d0];
                    float4 xr1 = *(const float4*)&XR[j*SP + d0 + 4];
                    float4 xi0 = *(const float4*)&XI[j*SP + d0];
                    float4 xi1 = *(const float4*)&XI[j*SP + d0 + 4];
                    ull gcd = pkdup(((const float*)&gc4)[jj]);
                    ull gsd = pkdup(((const float*)&gs4)[jj]);
                    a0 = fma2(gcd, pk2(xr0.x, xr0.y), a0);
                    a1 = fma2(gcd, pk2(xr0.z, xr0.w), a1);
                    a2 = fma2(gcd, pk2(xr1.x, xr1.y), a2);
                    a3 = fma2(gcd, pk2(xr1.z, xr1.w), a3);
                    a0 = fma2(gsd, pk2(xi0.x, xi0.y), a0);
                    a1 = fma2(gsd, pk2(xi0.z, xi0.w), a1);
                    a2 = fma2(gsd, pk2(xi1.x, xi1.y), a2);
                    a3 = fma2(gsd, pk2(xi1.z, xi1.w), a3);
                }
            }
            float2 f0 = up2(a0), f1 = up2(a1), f2 = up2(a2), f3 = up2(a3);
            float4 o0 = make_float4(f0.x, f0.y, f1.x, f1.y);
            float4 o1 = make_float4(f2.x, f2.y, f3.x, f3.y);
            *(float4*)&yg[t*64 + d0]           = o0;
            *(float4*)&yg[t*64 + d0 + 4]       = o1;
            *(float4*)&yg[(t+TH)*64 + d0]      = o0;
            *(float4*)&yg[(t+TH)*64 + d0 + 4]  = o1;
        }
    }
}

extern "C" void kernel_launch(void* const* d_in, const int* in_sizes, int n_in,
                              void* d_out, int out_size) {
    const float* x    = (const float*)d_in[0];
    const float* Wq_r = (const float*)d_in[1];
    const float* Wq_i = (const float*)d_in[2];
    const float* Wk_r = (const float*)d_in[3];
    const float* Wk_i = (const float*)d_in[4];
    const float* Wv_r = (const float*)d_in[5];
    const float* Wv_i = (const float*)d_in[6];
    const float* Wo_r = (const float*)d_in[7];
    const float* Wo_i = (const float*)d_in[8];
    float* y = (float*)d_out;

    cudaFuncSetAttribute(spectral_attn_kernel,
                         cudaFuncAttributeMaxDynamicSharedMemorySize, SMEM_BYTES);

    twiddle_init_kernel<<<(TH*64 + 255)/256, 256>>>();
    spectral_attn_kernel<<<GRID_BN, 256, SMEM_BYTES>>>(
        x, Wq_r, Wq_i, Wk_r, Wk_i, Wv_r, Wv_i, Wo_r, Wo_i, y);
}

// round 3
// speedup vs baseline: 1.2362x; 1.2362x over previous
#include <cuda_runtime.h>

typedef unsigned long long ull;

#define NB 8
#define NN 170
#define NT 336
#define TH 168          // folded length
#define GRID_BN (NB*NN) // 1360
#define SP 68           // padded row stride (floats)
#define SLOT 4368       // 64*68 + 16 pad

#define NTHREADS 512

// smem layout (floats):
//  [0..8)*SLOT : XR XI QR QI KTR KTI VTR VTI
//  W_OFF: WRs(4112) WIs(4112)
//  P_OFF: PRb(SLOT) PIb(SLOT)   split-K partials
//  PB_OFF: 16 warps * 128 softmax probs
#define W_OFF   (8*SLOT)
#define P_OFF   (W_OFF + 2*4112)
#define PB_OFF  (P_OFF + 2*SLOT)
#define SMEM_FLOATS (PB_OFF + 2048)
#define SMEM_BYTES  (SMEM_FLOATS*4)

// ------------------------------------------------------------------
// twiddle tables
// ------------------------------------------------------------------
__device__ float g_FC[TH*64];
__device__ float g_FS[TH*64];
__device__ float g_GC[TH*64];
__device__ float g_GS[TH*64];

__global__ void twiddle_init_kernel() {
    int idx = blockIdx.x * blockDim.x + threadIdx.x;
    if (idx >= TH*64) return;
    int t = idx >> 6;
    int j = idx & 63;
    int r = (t * j) % TH;
    float s, c;
    sincospif((float)r * (1.0f/84.0f), &s, &c);
    g_FC[idx] = c;
    g_FS[idx] = -s;
    float wj = (j == 0) ? (1.0f/336.0f) : (2.0f/336.0f);
    g_GC[idx] = wj * c;
    g_GS[idx] = -wj * s;
}

// ------------------------------------------------------------------
// packed f32x2 helpers
// ------------------------------------------------------------------
__device__ __forceinline__ ull pk2(float lo, float hi) {
    ull r;
    asm("mov.b64 %0, {%1, %2};" : "=l"(r) : "f"(lo), "f"(hi));
    return r;
}
__device__ __forceinline__ ull pkdup(float v) { return pk2(v, v); }
__device__ __forceinline__ ull fma2(ull a, ull b, ull c) {
    ull d;
    asm("fma.rn.f32x2 %0, %1, %2, %3;" : "=l"(d) : "l"(a), "l"(b), "l"(c));
    return d;
}
__device__ __forceinline__ float2 up2(ull v) {
    float2 f;
    asm("mov.b64 {%0, %1}, %2;" : "=f"(f.x), "=f"(f.y) : "l"(v));
    return f;
}
#define SGN2 0x8000000080000000ULL

__device__ __forceinline__ void stage_w(float* WRs, float* WIs,
                                        const float* wr, const float* wi, int tid) {
    #pragma unroll
    for (int k = 0; k < 2; k++) {
        int i = tid + k * NTHREADS;
        ((float4*)WRs)[i] = __ldg((const float4*)wr + i);
        ((float4*)WIs)[i] = __ldg((const float4*)wi + i);
    }
}

// ------------------------------------------------------------------
// split-K complex 64x64x64 GEMM over 512 threads.
// half 0 (tid<256): d=0..31 -> writes CR/CI
// half 1          : d=32..63 -> writes PR/PI
// then reduce CR += PR.
// TRANS=1: store transposed [e][m] stride SP.
// Includes the trailing __syncthreads()+reduction+__syncthreads().
// ------------------------------------------------------------------
template<int TRANS>
__device__ __forceinline__ void cgemm64_sk(
    const float* __restrict__ AR, const float* __restrict__ AI,
    const float* __restrict__ WR, const float* __restrict__ WI,
    float* __restrict__ CR, float* __restrict__ CI,
    float* __restrict__ PR, float* __restrict__ PI, int tid)
{
    const int half = tid >> 8;
    const int t2   = tid & 255;
    const int m0 = (t2 >> 4) * 4;
    const int e0 = (t2 & 15) * 4;
    const int dbase = half * 32;
    float* DR = half ? PR : CR;
    float* DI = half ? PI : CI;

    ull accR[4][2], accI[4][2];
    #pragma unroll
    for (int mm = 0; mm < 4; mm++) {
        accR[mm][0] = 0; accR[mm][1] = 0;
        accI[mm][0] = 0; accI[mm][1] = 0;
    }
    #pragma unroll 2
    for (int d4 = dbase; d4 < dbase + 32; d4 += 4) {
        float4 ar[4], ai[4];
        #pragma unroll
        for (int mm = 0; mm < 4; mm++) {
            ar[mm] = *(const float4*)&AR[(m0+mm)*SP + d4];
            ai[mm] = *(const float4*)&AI[(m0+mm)*SP + d4];
        }
        #pragma unroll
        for (int dd = 0; dd < 4; dd++) {
            float4 wr4 = *(const float4*)&WR[(d4+dd)*64 + e0];
            float4 wi4 = *(const float4*)&WI[(d4+dd)*64 + e0];
            ull wr0 = pk2(wr4.x, wr4.y), wr1 = pk2(wr4.z, wr4.w);
            ull wi0 = pk2(wi4.x, wi4.y), wi1 = pk2(wi4.z, wi4.w);
            ull nwi0 = wi0 ^ SGN2, nwi1 = wi1 ^ SGN2;
            #pragma unroll
            for (int mm = 0; mm < 4; mm++) {
                float a = ((const float*)&ar[mm])[dd];
                float b = ((const float*)&ai[mm])[dd];
                ull ad = pkdup(a), bd = pkdup(b);
                accR[mm][0] = fma2(ad, wr0,  accR[mm][0]);
                accR[mm][1] = fma2(ad, wr1,  accR[mm][1]);
                accI[mm][0] = fma2(ad, wi0,  accI[mm][0]);
                accI[mm][1] = fma2(ad, wi1,  accI[mm][1]);
                accR[mm][0] = fma2(bd, nwi0, accR[mm][0]);
                accR[mm][1] = fma2(bd, nwi1, accR[mm][1]);
                accI[mm][0] = fma2(bd, wr0,  accI[mm][0]);
                accI[mm][1] = fma2(bd, wr1,  accI[mm][1]);
            }
        }
    }
    #pragma unroll
    for (int mm = 0; mm < 4; mm++) {
        float2 r0 = up2(accR[mm][0]), r1 = up2(accR[mm][1]);
        float2 i0 = up2(accI[mm][0]), i1 = up2(accI[mm][1]);
        if (!TRANS) {
            *(float4*)&DR[(m0+mm)*SP + e0] = make_float4(r0.x, r0.y, r1.x, r1.y);
            *(float4*)&DI[(m0+mm)*SP + e0] = make_float4(i0.x, i0.y, i1.x, i1.y);
        } else {
            int m = m0 + mm;
            DR[(e0+0)*SP + m] = r0.x; DR[(e0+1)*SP + m] = r0.y;
            DR[(e0+2)*SP + m] = r1.x; DR[(e0+3)*SP + m] = r1.y;
            DI[(e0+0)*SP + m] = i0.x; DI[(e0+1)*SP + m] = i0.y;
            DI[(e0+2)*SP + m] = i1.x; DI[(e0+3)*SP + m] = i1.y;
        }
    }
    __syncthreads();
    // reduce partials: CR += PR, CI += PI over the full (incl. pad) region
    #pragma unroll 2
    for (int i = tid; i < 64*SP; i += NTHREADS) {
        CR[i] += PR[i];
        CI[i] += PI[i];
    }
    __syncthreads();
}

// ------------------------------------------------------------------
// main kernel: one CTA (512 threads) per (b, n)
// ------------------------------------------------------------------
__global__ void __launch_bounds__(NTHREADS, 1) spectral_attn_kernel(
    const float* __restrict__ x,
    const float* __restrict__ Wq_r, const float* __restrict__ Wq_i,
    const float* __restrict__ Wk_r, const float* __restrict__ Wk_i,
    const float* __restrict__ Wv_r, const float* __restrict__ Wv_i,
    const float* __restrict__ Wv_r2, const float* __restrict__ Wv_i2, // Wo
    float* __restrict__ y)
{
    extern __shared__ float sm[];
    float* XR   = sm;
    float* XI   = sm + 1*SLOT;
    float* QRb  = sm + 2*SLOT;
    float* QIb  = sm + 3*SLOT;
    float* KTRb = sm + 4*SLOT;   // K^T [e][m]; later OUT [l][e]
    float* KTIb = sm + 5*SLOT;
    float* VTRb = sm + 6*SLOT;   // V^T [e][m]
    float* VTIb = sm + 7*SLOT;
    float* WRs  = sm + W_OFF;
    float* WIs  = sm + W_OFF + 4112;
    float* PRb  = sm + P_OFF;
    float* PIb  = sm + P_OFF + SLOT;
    float* PB   = sm + PB_OFF;
    float* xs   = QRb;           // 168x64 fold buffer (alias)

    const int tid = threadIdx.x;
    const int bn  = blockIdx.x;
    const float* xg = x + (size_t)bn * (NT*64);
    float*       yg = y + (size_t)bn * (NT*64);
    const float* Wo_r = Wv_r2;
    const float* Wo_i = Wv_i2;

    // ---- Phase 0: fold x[t] + x[t+168] ----
    for (int i = tid; i < TH*16; i += NTHREADS) {
        int t = i >> 4, c = i & 15;
        float4 a = __ldg((const float4*)(xg + t*64) + c);
        float4 b = __ldg((const float4*)(xg + (t+TH)*64) + c);
        *(float4*)&xs[t*64 + c*4] = make_float4(a.x+b.x, a.y+b.y, a.z+b.z, a.w+b.w);
    }
    __syncthreads();

    // ---- Phase 1: forward DFT  X[j,d] = sum_t xs[t,d] * (FC + i FS) ----
    {
        const int j0 = (tid >> 4) * 2;      // 32 j-groups of 2
        const int d0 = (tid & 15) * 4;      // 16 d-groups of 4
        ull aR[2][2], aI[2][2];
        #pragma unroll
        for (int jj = 0; jj < 2; jj++) { aR[jj][0]=0; aR[jj][1]=0; aI[jj][0]=0; aI[jj][1]=0; }
        #pragma unroll 4
        for (int t = 0; t < TH; t++) {
            float2 c2 = __ldg((const float2*)&g_FC[t*64 + j0]);
            float2 s2 = __ldg((const float2*)&g_FS[t*64 + j0]);
            float4 xv = *(const float4*)&xs[t*64 + d0];
            ull x01 = pk2(xv.x, xv.y), x23 = pk2(xv.z, xv.w);
            ull c0 = pkdup(c2.x), c1 = pkdup(c2.y);
            ull s0 = pkdup(s2.x), s1 = pkdup(s2.y);
            aR[0][0] = fma2(c0, x01, aR[0][0]);
            aR[0][1] = fma2(c0, x23, aR[0][1]);
            aI[0][0] = fma2(s0, x01, aI[0][0]);
            aI[0][1] = fma2(s0, x23, aI[0][1]);
            aR[1][0] = fma2(c1, x01, aR[1][0]);
            aR[1][1] = fma2(c1, x23, aR[1][1]);
            aI[1][0] = fma2(s1, x01, aI[1][0]);
            aI[1][1] = fma2(s1, x23, aI[1][1]);
        }
        #pragma unroll
        for (int jj = 0; jj < 2; jj++) {
            float2 r0 = up2(aR[jj][0]), r1 = up2(aR[jj][1]);
            float2 i0 = up2(aI[jj][0]), i1 = up2(aI[jj][1]);
            *(float4*)&XR[(j0+jj)*SP + d0] = make_float4(r0.x, r0.y, r1.x, r1.y);
            *(float4*)&XI[(j0+jj)*SP + d0] = make_float4(i0.x, i0.y, i1.x, i1.y);
        }
    }
    // ordering of xs-reads vs QRb-writes is provided by the stage_w sync below

    // ---- Phase 2: two attention layers ----
    const int wid = tid >> 5, ln = tid & 31;
    #pragma unroll 1
    for (int layer = 0; layer < 2; layer++) {
        const float* wq_r = Wq_r + layer*4096; const float* wq_i = Wq_i + layer*4096;
        const float* wk_r = Wk_r + layer*4096; const float* wk_i = Wk_i + layer*4096;
        const float* wv_r = Wv_r + layer*4096; const float* wv_i = Wv_i + layer*4096;
        const float* wo_r = Wo_r + layer*4096; const float* wo_i = Wo_i + layer*4096;

        stage_w(WRs, WIs, wq_r, wq_i, tid); __syncthreads();
        cgemm64_sk<0>(XR, XI, WRs, WIs, QRb, QIb, PRb, PIb, tid);

        stage_w(WRs, WIs, wk_r, wk_i, tid); __syncthreads();
        cgemm64_sk<1>(XR, XI, WRs, WIs, KTRb, KTIb, PRb, PIb, tid);

        stage_w(WRs, WIs, wv_r, wv_i, tid); __syncthreads();
        cgemm64_sk<1>(XR, XI, WRs, WIs, VTRb, VTIb, PRb, PIb, tid);

        // ---- fused scores -> softmax -> AV; 2 warps per head, 32 rows each ----
        {
            const int h = wid >> 1;
            const int lbase = (wid & 1) * 32;
            ull kpr[8], kpi[8];
            #pragma unroll
            for (int d = 0; d < 8; d++) {
                const float* pr = KTRb + (h*8+d)*SP;
                const float* pi = KTIb + (h*8+d)*SP;
                kpr[d] = pk2(pr[ln], pr[ln+32]);
                kpi[d] = pk2(pi[ln], pi[ln+32]);
            }
            __syncthreads();   // K safely in registers before OUT overwrites
            float* OUTR = KTRb;
            float* OUTI = KTIb;
            float* Pw = PB + wid*128;

            const int rhalf = ln >> 4;
            const int qq = ln & 15;
            const int dAV = qq & 7;
            const bool isI = (qq & 8) != 0;
            const float* vrow = (isI ? VTIb : VTRb) + (h*8 + dAV)*SP;
            float* orow = isI ? OUTI : OUTR;

            const float SCALE = 0.3535533905932738f; // 1/sqrt(8)
            for (int l = lbase; l < lbase + 32; l += 2) {
                float sA[2], sB[2];
                #pragma unroll
                for (int r = 0; r < 2; r++) {
                    int row = l + r;
                    float4 qr0 = *(const float4*)&QRb[row*SP + h*8];
                    float4 qr1 = *(const float4*)&QRb[row*SP + h*8 + 4];
                    float4 qi0 = *(const float4*)&QIb[row*SP + h*8];
                    float4 qi1 = *(const float4*)&QIb[row*SP + h*8 + 4];
                    ull a0 = 0, a1 = 0, a2 = 0, a3 = 0;
                    a0 = fma2(pkdup(qr0.x), kpr[0], a0);
                    a1 = fma2(pkdup(qr0.y), kpr[1], a1);
                    a2 = fma2(pkdup(qr0.z), kpr[2], a2);
                    a3 = fma2(pkdup(qr0.w), kpr[3], a3);
                    a0 = fma2(pkdup(qr1.x), kpr[4], a0);
                    a1 = fma2(pkdup(qr1.y), kpr[5], a1);
                    a2 = fma2(pkdup(qr1.z), kpr[6], a2);
                    a3 = fma2(pkdup(qr1.w), kpr[7], a3);
                    a0 = fma2(pkdup(qi0.x), kpi[0], a0);
                    a1 = fma2(pkdup(qi0.y), kpi[1], a1);
                    a2 = fma2(pkdup(qi0.z), kpi[2], a2);
                    a3 = fma2(pkdup(qi0.w), kpi[3], a3);
                    a0 = fma2(pkdup(qi1.x), kpi[4], a0);
                    a1 = fma2(pkdup(qi1.y), kpi[5], a1);
                    a2 = fma2(pkdup(qi1.z), kpi[6], a2);
                    a3 = fma2(pkdup(qi1.w), kpi[7], a3);
                    float2 f0 = up2(a0), f1 = up2(a1), f2 = up2(a2), f3 = up2(a3);
                    sA[r] = ((f0.x+f1.x)+(f2.x+f3.x)) * SCALE;
                    sB[r] = ((f0.y+f1.y)+(f2.y+f3.y)) * SCALE;
                }
                float mx0 = fmaxf(sA[0], sB[0]);
                float mx1 = fmaxf(sA[1], sB[1]);
                #pragma unroll
                for (int o = 16; o; o >>= 1) {
                    mx0 = fmaxf(mx0, __shfl_xor_sync(0xffffffffu, mx0, o));
                    mx1 = fmaxf(mx1, __shfl_xor_sync(0xffffffffu, mx1, o));
                }
                float e00 = __expf(sA[0]-mx0), e01 = __expf(sB[0]-mx0);
                float e10 = __expf(sA[1]-mx1), e11 = __expf(sB[1]-mx1);
                float su0 = e00 + e01, su1 = e10 + e11;
                #pragma unroll
                for (int o = 16; o; o >>= 1) {
                    su0 += __shfl_xor_sync(0xffffffffu, su0, o);
                    su1 += __shfl_xor_sync(0xffffffffu, su1, o);
                }
                float inv0 = 1.0f / su0, inv1 = 1.0f / su1;
                Pw[ln]       = e00 * inv0;  Pw[ln+32]    = e01 * inv0;
                Pw[64+ln]    = e10 * inv1;  Pw[64+ln+32] = e11 * inv1;
                __syncwarp();
                const float* pr = Pw + rhalf*64;
                float ac0 = 0.0f, ac1 = 0.0f;
                #pragma unroll
                for (int m4 = 0; m4 < 64; m4 += 8) {
                    float4 p4 = *(const float4*)&pr[m4];
                    float4 v4 = *(const float4*)&vrow[m4];
                    ac0 = fmaf(p4.x, v4.x, ac0); ac0 = fmaf(p4.y, v4.y, ac0);
                    ac0 = fmaf(p4.z, v4.z, ac0); ac0 = fmaf(p4.w, v4.w, ac0);
                    float4 p5 = *(const float4*)&pr[m4+4];
                    float4 v5 = *(const float4*)&vrow[m4+4];
                    ac1 = fmaf(p5.x, v5.x, ac1); ac1 = fmaf(p5.y, v5.y, ac1);
                    ac1 = fmaf(p5.z, v5.z, ac1); ac1 = fmaf(p5.w, v5.w, ac1);
                }
                orow[(l+rhalf)*SP + h*8 + dAV] = ac0 + ac1;
                __syncwarp();
            }
        }
        // ---- Wo GEMM: X = OUT * Wo ----
        stage_w(WRs, WIs, wo_r, wo_i, tid); __syncthreads();
        cgemm64_sk<0>(KTRb, KTIb, WRs, WIs, XR, XI, PRb, PIb, tid);
    }

    // ---- Phase 3: inverse DFT, period-168 output stored twice ----
    {
        const int tg = tid >> 4;            // 32 t-lanes
        const int d0 = (tid & 15) * 4;      // 16 d-groups of 4
        for (int t = tg; t < TH; t += 32) {
            ull a0 = 0, a1 = 0;
            #pragma unroll 4
            for (int j4 = 0; j4 < 64; j4 += 4) {
                float4 gc4 = __ldg((const float4*)&g_GC[t*64 + j4]);
                float4 gs4 = __ldg((const float4*)&g_GS[t*64 + j4]);
                #pragma unroll
                for (int jj = 0; jj < 4; jj++) {
                    int j = j4 + jj;
                    float4 xr0 = *(const float4*)&XR[j*SP + d0];
                    float4 xi0 = *(const float4*)&XI[j*SP + d0];
                    ull gcd = pkdup(((const float*)&gc4)[jj]);
                    ull gsd = pkdup(((const float*)&gs4)[jj]);
                    a0 = fma2(gcd, pk2(xr0.x, xr0.y), a0);
                    a1 = fma2(gcd, pk2(xr0.z, xr0.w), a1);
                    a0 = fma2(gsd, pk2(xi0.x, xi0.y), a0);
                    a1 = fma2(gsd, pk2(xi0.z, xi0.w), a1);
                }
            }
            float2 f0 = up2(a0), f1 = up2(a1);
            float4 o0 = make_float4(f0.x, f0.y, f1.x, f1.y);
            *(float4*)&yg[t*64 + d0]      = o0;
            *(float4*)&yg[(t+TH)*64 + d0] = o0;
        }
    }
}

extern "C" void kernel_launch(void* const* d_in, const int* in_sizes, int n_in,
                              void* d_out, int out_size) {
    const float* x    = (const float*)d_in[0];
    const float* Wq_r = (const float*)d_in[1];
    const float* Wq_i = (const float*)d_in[2];
    const float* Wk_r = (const float*)d_in[3];
    const float* Wk_i = (const float*)d_in[4];
    const float* Wv_r = (const float*)d_in[5];
    const float* Wv_i = (const float*)d_in[6];
    const float* Wo_r = (const float*)d_in[7];
    const float* Wo_i = (const float*)d_in[8];
    float* y = (float*)d_out;

    cudaFuncSetAttribute(spectral_attn_kernel,
                         cudaFuncAttributeMaxDynamicSharedMemorySize, SMEM_BYTES);

    twiddle_init_kernel<<<(TH*64 + 255)/256, 256>>>();
    spectral_attn_kernel<<<GRID_BN, NTHREADS, SMEM_BYTES>>>(
        x, Wq_r, Wq_i, Wk_r, Wk_i, Wv_r, Wv_i, Wo_r, Wo_i, y);
}